// round 17
// baseline (speedup 1.0000x reference)
#include <cuda_runtime.h>
#include <cuda.h>
#include <cuda_bf16.h>
#include <cstdint>

// Problem constants
#define BSZ   2048
#define D     2048
#define MM    6
#define THRESH 30
#define LAM   1.0e-4f
#define LDF   (MM*D)          // 12288
#define NITER (THRESH-1)      // 29

// GEMM tiling
#define TMt   128
#define TNt   256
#define TKt   64              // 64 bf16 = 128B rows, SW128
#define KITERS (D / TKt)      // 32
#define A_BYTES (TMt * TKt * 2)              // 16384
#define W_BYTES (TNt * TKt * 2)              // 32768
#define STAGE_BYTES (2*A_BYTES + 2*W_BYTES)  // 98304
#define SMEM_TOTAL (2*STAGE_BYTES + 2048)

// ---------------- device scratch ----------------
__device__ float         g_F[(size_t)BSZ * MM * D];
__device__ float         g_G[(size_t)BSZ * MM * D];   // G = F - X history
__device__ __nv_bfloat16 g_Ahi[(size_t)BSZ * D];
__device__ __nv_bfloat16 g_Alo[(size_t)BSZ * D];
__device__ __nv_bfloat16 g_Whi[(size_t)D * D];        // [N,K] transposed
__device__ __nv_bfloat16 g_Wlo[(size_t)D * D];
__device__ double        g_norms[2 * NITER + 2];
__device__ unsigned      g_bar[16];                    // per-row barrier counters
__device__ unsigned      g_prog[16];                   // per-row combine-chunk progress

// ---------------- PTX helpers ----------------
__device__ __forceinline__ uint32_t smem_u32(const void* p) {
    uint32_t a;
    asm("{ .reg .u64 t; cvta.to.shared.u64 t, %1; cvt.u32.u64 %0, t; }" : "=r"(a) : "l"(p));
    return a;
}
#define MBAR_INIT(a, c) asm volatile("mbarrier.init.shared.b64 [%0], %1;" :: "r"(a), "r"(c) : "memory")
#define MBAR_EXPECT_TX(a, b) asm volatile("mbarrier.arrive.expect_tx.shared.b64 _, [%0], %1;" :: "r"(a), "r"(b) : "memory")
#define MBAR_ARRIVE(a) asm volatile("mbarrier.arrive.shared.b64 _, [%0];" :: "r"(a) : "memory")
#define MBAR_WAIT(a, ph) do { \
    uint32_t _m = (a); uint32_t _p = (ph); \
    asm volatile("{\n\t.reg .pred P1;\n\tWL_%=:\n\t" \
        "mbarrier.try_wait.parity.acquire.cta.shared::cta.b64 P1, [%0], %1, 0x989680;\n\t" \
        "@P1 bra.uni WD_%=;\n\tbra.uni WL_%=;\n\tWD_%=:\n\t}" \
        :: "r"(_m), "r"(_p) : "memory"); \
} while (0)
#define FENCE_PROXY_ASYNC() asm volatile("fence.proxy.async;" ::: "memory")

__device__ __forceinline__ void tma2d(uint32_t dst, const CUtensorMap* tm, int x, int y, uint32_t bar) {
    asm volatile(
        "cp.async.bulk.tensor.2d.shared::cta.global.tile.mbarrier::complete_tx::bytes "
        "[%0], [%1, {%2, %3}], [%4];"
        :: "r"(dst), "l"(tm), "r"(x), "r"(y), "r"(bar) : "memory");
}

#define LDSM4(r, addr) \
    asm volatile("ldmatrix.sync.aligned.m8n8.x4.shared.b16 {%0,%1,%2,%3}, [%4];" \
        : "=r"((r)[0]), "=r"((r)[1]), "=r"((r)[2]), "=r"((r)[3]) : "r"(addr))

#define MMA16816(d, a, b0, b1) \
    asm("mma.sync.aligned.m16n8k16.row.col.f32.bf16.bf16.f32 " \
        "{%0,%1,%2,%3}, {%4,%5,%6,%7}, {%8,%9}, {%0,%1,%2,%3};" \
        : "+f"((d)[0]), "+f"((d)[1]), "+f"((d)[2]), "+f"((d)[3]) \
        : "r"((a)[0]), "r"((a)[1]), "r"((a)[2]), "r"((a)[3]), "r"(b0), "r"(b1))

__device__ __forceinline__ void split32(float v, __nv_bfloat16& hi, __nv_bfloat16& lo) {
    hi = __float2bfloat16(v);
    lo = __float2bfloat16(v - __bfloat162float(hi));
}

__device__ __forceinline__ float fast_tanh(float x) {
    float ax = fabsf(x);
    float e = __expf(2.0f * ax);
    float r = 1.0f - __fdividef(2.0f, e + 1.0f);
    return copysignf(r, x);
}

// one combine chunk: d in [128p, 128p+128) for this warp's batch b
__device__ __forceinline__ void combine_chunk(
    int p, int b, int n, int up, int last,
    const float* __restrict__ Fall, float* __restrict__ Xall,
    float* __restrict__ res,
    __nv_bfloat16* __restrict__ Ahi, __nv_bfloat16* __restrict__ Alo,
    const float* s_al, int lane)
{
    const float4* Fb = (const float4*)(Fall + (size_t)b * LDF);
    int c4 = lane + 32 * p;
    float4 xv = make_float4(0.f, 0.f, 0.f, 0.f);
    #pragma unroll
    for (int j = 0; j < 6; j++) {
        if (j < n) {
            float a = s_al[j];
            float4 f = Fb[j * 512 + c4];
            xv.x += a * f.x; xv.y += a * f.y; xv.z += a * f.z; xv.w += a * f.w;
        }
    }
    ((float4*)(Xall + (size_t)b * LDF + up * D))[c4] = xv;
    if (last)
        ((float4*)(res + (size_t)b * D))[c4] = xv;
    __nv_bfloat16 h0, l0, h1, l1, h2, l2, h3, l3;
    split32(xv.x, h0, l0); split32(xv.y, h1, l1);
    split32(xv.z, h2, l2); split32(xv.w, h3, l3);
    __nv_bfloat162* Ah = (__nv_bfloat162*)(Ahi + (size_t)b * D);
    __nv_bfloat162* Al = (__nv_bfloat162*)(Alo + (size_t)b * D);
    Ah[c4 * 2]     = __nv_bfloat162(h0, h1);
    Ah[c4 * 2 + 1] = __nv_bfloat162(h2, h3);
    Al[c4 * 2]     = __nv_bfloat162(l0, l1);
    Al[c4 * 2 + 1] = __nv_bfloat162(l2, l3);
}

// ---------------- persistent fused AA kernel ----------------
__global__ __launch_bounds__(512, 1)
void aa_persistent_kernel(const __grid_constant__ CUtensorMap tmAhi,
                          const __grid_constant__ CUtensorMap tmAlo,
                          const __grid_constant__ CUtensorMap tmWhi,
                          const __grid_constant__ CUtensorMap tmWlo,
                          const float* __restrict__ bias,
                          float* __restrict__ Fall,
                          float* __restrict__ Gall,
                          float* __restrict__ Xall,
                          __nv_bfloat16* __restrict__ Ahi,
                          __nv_bfloat16* __restrict__ Alo,
                          float* __restrict__ res,
                          double* __restrict__ norms,
                          unsigned* __restrict__ barcnt,
                          unsigned* __restrict__ prog)
{
    extern __shared__ char smem[];
    __shared__ float red[2][16];
    __shared__ float s_alpha[16][6];
    const uint32_t sb = smem_u32(smem);
    const uint32_t stage0 = (sb + 1024 + 1023) & ~1023u;   // SW128: 1024-aligned tiles
    const int tid = threadIdx.x;
    const int lane = tid & 31;
    const int w = tid >> 5;
    const int wm = w & 3;
    const int wn = w >> 2;
    const int bm = blockIdx.y * TMt;
    const int bn = blockIdx.x * TNt;
    const int myb = (blockIdx.y * 8 + blockIdx.x) * 16 + w;  // this warp's batch

    const uint32_t FULL[2]  = { sb,      sb + 8  };
    const uint32_t EMPTY[2] = { sb + 16, sb + 24 };

    if (tid == 0) {
        MBAR_INIT(FULL[0], 1);  MBAR_INIT(FULL[1], 1);
        MBAR_INIT(EMPTY[0], 16); MBAR_INIT(EMPTY[1], 16);
    }
    __syncthreads();

    const uint32_t xorv = (uint32_t)(lane & 7) << 4;
    const uint32_t a_r = lane & 15;
    const uint32_t a_b = (uint32_t)(lane >> 4) << 4;
    const uint32_t b_r = ((uint32_t)(lane >> 4) << 3) + (lane & 7);
    const uint32_t b_b = (uint32_t)((lane >> 3) & 1) << 4;

    unsigned target = 0;

    for (int it = 0; it < THRESH; it++) {
        const int n = (it < MM) ? it : MM;
        const int up = it % MM;
        const int last = (it == THRESH - 1);
        float* C = Fall + up * D;
        const float* Xcur = Xall + up * D;
        float* Gout = Gall + up * D;
        double* norms_slot = (it > 0) ? (norms + 2 * (it - 1)) : nullptr;
        const unsigned pbase = (unsigned)((it - 1) * 128);   // prog base for it>=1

        // W prefetch (independent of step phase)
        if (tid == 0) {
            #pragma unroll
            for (int s = 0; s < 2; s++) {
                uint32_t st = stage0 + s * STAGE_BYTES;
                MBAR_EXPECT_TX(FULL[s], STAGE_BYTES);
                tma2d(st + 2 * A_BYTES,           &tmWhi, s * TKt, bn, FULL[s]);
                tma2d(st + 2 * A_BYTES + W_BYTES, &tmWlo, s * TKt, bn, FULL[s]);
            }
        }

        // ---------------- step phase: gram + solve + combine chunks 0,1 ----------------
        if (it > 0) {
            const float4* Gb = (const float4*)(Gall + (size_t)myb * LDF);

            float acc[21];
            #pragma unroll
            for (int p = 0; p < 21; p++) acc[p] = 0.f;

            #pragma unroll 4
            for (int p = 0; p < 16; p++) {
                int c4 = lane + 32 * p;
                float4 g4[6];
                #pragma unroll
                for (int j = 0; j < 6; j++) {
                    if (j < n) g4[j] = Gb[j * 512 + c4];
                    else g4[j] = make_float4(0.f, 0.f, 0.f, 0.f);
                }
                int q = 0;
                #pragma unroll
                for (int i = 0; i < 6; i++)
                    #pragma unroll
                    for (int j = i; j < 6; j++) {
                        acc[q] += g4[i].x * g4[j].x + g4[i].y * g4[j].y
                                + g4[i].z * g4[j].z + g4[i].w * g4[j].w;
                        q++;
                    }
            }
            #pragma unroll
            for (int s = 16; s > 0; s >>= 1)
                #pragma unroll
                for (int p = 0; p < 21; p++)
                    acc[p] += __shfl_xor_sync(0xFFFFFFFF, acc[p], s);

            // register Cholesky -> alpha -> smem
            {
                float A[6][6];
                int q = 0;
                #pragma unroll
                for (int i = 0; i < 6; i++)
                    #pragma unroll
                    for (int j = i; j < 6; j++) {
                        float v = acc[q++];
                        if (i == j) v += LAM;
                        A[i][j] = v; A[j][i] = v;
                    }
                #pragma unroll
                for (int c = 0; c < 6; c++) {
                    if (c < n) {
                        float d = A[c][c];
                        #pragma unroll
                        for (int m = 0; m < 6; m++) if (m < c) d -= A[c][m] * A[c][m];
                        d = fmaxf(d, 1e-12f);
                        float lcc = sqrtf(d);
                        A[c][c] = lcc;
                        float inv = __fdividef(1.f, lcc);
                        #pragma unroll
                        for (int r = 0; r < 6; r++) {
                            if (r > c && r < n) {
                                float sdot = A[r][c];
                                #pragma unroll
                                for (int m = 0; m < 6; m++) if (m < c) sdot -= A[r][m] * A[c][m];
                                A[r][c] = sdot * inv;
                            }
                        }
                    }
                }
                float y[6];
                #pragma unroll
                for (int c = 0; c < 6; c++) {
                    float v = 1.f;
                    #pragma unroll
                    for (int m = 0; m < 6; m++) if (m < c) v -= A[c][m] * y[m];
                    y[c] = (c < n) ? __fdividef(v, A[c][c]) : 0.f;
                }
                float z[6];
                #pragma unroll
                for (int c = 5; c >= 0; c--) {
                    float v = y[c];
                    #pragma unroll
                    for (int m = 0; m < 6; m++) if (m > c) v -= A[m][c] * z[m];
                    z[c] = (c < n) ? __fdividef(v, A[c][c]) : 0.f;
                }
                float ssum = z[0] + z[1] + z[2] + z[3] + z[4] + z[5];
                float invs = __fdividef(1.f, ssum);
                if (lane == 0) {
                    #pragma unroll
                    for (int j = 0; j < 6; j++) s_alpha[w][j] = z[j] * invs;
                }
                __syncwarp();
            }

            // combine chunks 0,1 now (cover K cols 0..255 -> prologue + first prefetches)
            combine_chunk(0, myb, n, up, last, Fall, Xall, res, Ahi, Alo, s_alpha[w], lane);
            combine_chunk(1, myb, n, up, last, Fall, Xall, res, Ahi, Alo, s_alpha[w], lane);
            __threadfence();
            __syncthreads();
            if (tid == 0) atomicAdd(&prog[blockIdx.y], 2u);
        }

        // A TMA stages 0,1 (wait chunks 0,1 from all 8 row CTAs)
        if (tid == 0) {
            if (it > 0) {
                volatile unsigned* pc = &prog[blockIdx.y];
                while (*pc < pbase + 16u) { __nanosleep(64); }
                FENCE_PROXY_ASYNC();
            }
            #pragma unroll
            for (int s = 0; s < 2; s++) {
                uint32_t st = stage0 + s * STAGE_BYTES;
                tma2d(st,           &tmAhi, s * TKt, bm, FULL[s]);
                tma2d(st + A_BYTES, &tmAlo, s * TKt, bm, FULL[s]);
            }
        }

        float accm[2][8][4];
        #pragma unroll
        for (int mt = 0; mt < 2; mt++)
            #pragma unroll
            for (int nt = 0; nt < 8; nt++)
                #pragma unroll
                for (int q = 0; q < 4; q++) accm[mt][nt][q] = 0.f;

        for (int i = 0; i < KITERS; i++) {
            const int buf = i & 1;
            const int ph = (i >> 1) & 1;
            MBAR_WAIT(FULL[buf], ph);

            const uint32_t st = stage0 + buf * STAGE_BYTES;
            const uint32_t Ahi_b = st;
            const uint32_t Alo_b = st + A_BYTES;
            const uint32_t Whi_b = st + 2 * A_BYTES;
            const uint32_t Wlo_b = st + 2 * A_BYTES + W_BYTES;

            #pragma unroll
            for (int k16 = 0; k16 < 4; k16++) {
                uint32_t ahi[2][4], alo[2][4];
                #pragma unroll
                for (int mt = 0; mt < 2; mt++) {
                    uint32_t R = wm * 32 + mt * 16 + a_r;
                    uint32_t B = a_b + k16 * 32;
                    uint32_t off = R * 128 + (B ^ xorv);
                    LDSM4(ahi[mt], Ahi_b + off);
                    LDSM4(alo[mt], Alo_b + off);
                }
                #pragma unroll
                for (int p = 0; p < 4; p++) {
                    uint32_t R = wn * 64 + p * 16 + b_r;
                    uint32_t B = b_b + k16 * 32;
                    uint32_t off = R * 128 + (B ^ xorv);
                    uint32_t wh[4], wl[4];
                    LDSM4(wh, Whi_b + off);
                    LDSM4(wl, Wlo_b + off);
                    #pragma unroll
                    for (int mt = 0; mt < 2; mt++)
                        #pragma unroll
                        for (int q = 0; q < 2; q++)
                            MMA16816(accm[mt][2 * p + q], ahi[mt], wh[2 * q], wh[2 * q + 1]);
                    #pragma unroll
                    for (int mt = 0; mt < 2; mt++)
                        #pragma unroll
                        for (int q = 0; q < 2; q++)
                            MMA16816(accm[mt][2 * p + q], ahi[mt], wl[2 * q], wl[2 * q + 1]);
                    #pragma unroll
                    for (int mt = 0; mt < 2; mt++)
                        #pragma unroll
                        for (int q = 0; q < 2; q++)
                            MMA16816(accm[mt][2 * p + q], alo[mt], wh[2 * q], wh[2 * q + 1]);
                }
            }
            if (lane == 0) MBAR_ARRIVE(EMPTY[buf]);

            // pipelined combine: chunk i+1 during mainloop iters 1..14
            if (it > 0 && i >= 1 && i <= 14) {
                combine_chunk(i + 1, myb, n, up, last, Fall, Xall, res, Ahi, Alo,
                              s_alpha[w], lane);
                __threadfence();
                __syncthreads();
                if (tid == 0) atomicAdd(&prog[blockIdx.y], 1u);
            }

            if (tid == 0 && i + 2 < KITERS) {
                MBAR_WAIT(EMPTY[buf], ph);
                MBAR_EXPECT_TX(FULL[buf], STAGE_BYTES);
                int k0 = (i + 2) * TKt;
                if (it > 0) {
                    unsigned need = pbase + 8u * (unsigned)(((i + 2) >> 1) + 1);
                    volatile unsigned* pc = &prog[blockIdx.y];
                    while (*pc < need) { __nanosleep(64); }
                    FENCE_PROXY_ASYNC();
                }
                tma2d(st,                         &tmAhi, k0, bm, FULL[buf]);
                tma2d(st + A_BYTES,               &tmAlo, k0, bm, FULL[buf]);
                tma2d(st + 2 * A_BYTES,           &tmWhi, k0, bn, FULL[buf]);
                tma2d(st + 2 * A_BYTES + W_BYTES, &tmWlo, k0, bn, FULL[buf]);
            }
        }
        // drain the last two EMPTY phases so parity is consistent next iteration
        if (tid == 0) {
            MBAR_WAIT(EMPTY[0], ((KITERS - 2) >> 1) & 1);
            MBAR_WAIT(EMPTY[1], ((KITERS - 1) >> 1) & 1);
        }

        // epilogue: bias + tanh -> F; g = f - x -> G; norms
        const int r_in = lane >> 2;
        const int c_in = (lane & 3) * 2;
        float sg = 0.f, sf = 0.f;
        #pragma unroll
        for (int mt = 0; mt < 2; mt++) {
            const int row = bm + wm * 32 + mt * 16 + r_in;
            #pragma unroll
            for (int nt = 0; nt < 8; nt++) {
                const int col = bn + wn * 64 + nt * 8 + c_in;
                float2 bb = *(const float2*)(bias + col);
                float v0 = fast_tanh(accm[mt][nt][0] + bb.x);
                float v1 = fast_tanh(accm[mt][nt][1] + bb.y);
                float v2 = fast_tanh(accm[mt][nt][2] + bb.x);
                float v3 = fast_tanh(accm[mt][nt][3] + bb.y);
                size_t o0 = (size_t)row * LDF + col;
                size_t o1 = (size_t)(row + 8) * LDF + col;
                float2 x0 = *(const float2*)(Xcur + o0);
                float2 x1 = *(const float2*)(Xcur + o1);
                float g0 = v0 - x0.x, g1 = v1 - x0.y;
                float g2 = v2 - x1.x, g3 = v3 - x1.y;
                *(float2*)(C + o0) = make_float2(v0, v1);
                *(float2*)(C + o1) = make_float2(v2, v3);
                *(float2*)(Gout + o0) = make_float2(g0, g1);
                *(float2*)(Gout + o1) = make_float2(g2, g3);
                sg += g0 * g0 + g1 * g1 + g2 * g2 + g3 * g3;
                sf += v0 * v0 + v1 * v1 + v2 * v2 + v3 * v3;
            }
        }
        if (norms_slot != nullptr) {
            #pragma unroll
            for (int s = 16; s > 0; s >>= 1) {
                sg += __shfl_xor_sync(0xFFFFFFFF, sg, s);
                sf += __shfl_xor_sync(0xFFFFFFFF, sf, s);
            }
            if (lane == 0) { red[0][w] = sg; red[1][w] = sf; }
            __syncthreads();
            if (w == 0 && lane < 16) {
                float a = red[0][lane], b = red[1][lane];
                #pragma unroll
                for (int s = 8; s > 0; s >>= 1) {
                    a += __shfl_xor_sync(0xFFFF, a, s);
                    b += __shfl_xor_sync(0xFFFF, b, s);
                }
                if (lane == 0) {
                    atomicAdd(&norms_slot[0], (double)a);
                    atomicAdd(&norms_slot[1], (double)b);
                }
            }
        }

        // post-epilogue row barrier (F/G visible to next step)
        if (it < THRESH - 1) {
            __syncthreads();
            __threadfence();
            target += 8;
            if (tid == 0) {
                atomicAdd(&barcnt[blockIdx.y], 1u);
                volatile unsigned* c = &barcnt[blockIdx.y];
                while (*c < target) { __nanosleep(64); }
            }
            __syncthreads();
        }
    }
}

// ---------------- W transpose + bf16 split ----------------
__global__ __launch_bounds__(1024)
void wsplit_kernel(const float* __restrict__ W,
                   __nv_bfloat16* __restrict__ Whi, __nv_bfloat16* __restrict__ Wlo)
{
    __shared__ float t[32][33];
    int n0 = blockIdx.x * 32, k0 = blockIdx.y * 32;
    t[threadIdx.y][threadIdx.x] = W[(size_t)(k0 + threadIdx.y) * D + n0 + threadIdx.x];
    __syncthreads();
    float v = t[threadIdx.x][threadIdx.y];
    __nv_bfloat16 hi, lo; split32(v, hi, lo);
    size_t o = (size_t)(n0 + threadIdx.y) * D + k0 + threadIdx.x;
    Whi[o] = hi; Wlo[o] = lo;
}

// ---------------- small utility kernels ----------------
__global__ void zero_norms_kernel(double* norms, unsigned* bar, unsigned* prog) {
    int i = threadIdx.x;
    if (i < 2 * NITER + 2) norms[i] = 0.0;
    if (i < 16) { bar[i] = 0u; prog[i] = 0u; }
}

__global__ void scatter_x0_kernel(const float* __restrict__ x0, float* __restrict__ X,
                                  __nv_bfloat16* __restrict__ Ahi, __nv_bfloat16* __restrict__ Alo) {
    int idx = blockIdx.x * blockDim.x + threadIdx.x;
    if (idx >= BSZ * D) return;
    int b = idx >> 11;
    int c = idx & (D - 1);
    float v = x0[idx];
    X[(size_t)b * LDF + c] = v;
    __nv_bfloat16 hi, lo; split32(v, hi, lo);
    Ahi[idx] = hi; Alo[idx] = lo;
}

__global__ void trace_kernel(const double* __restrict__ norms,
                             float* __restrict__ rel, float* __restrict__ absd)
{
    int k = threadIdx.x;
    if (k < NITER) {
        double a = sqrt(norms[2 * k]);
        double fn = sqrt(norms[2 * k + 1]);
        absd[k] = (float)a;
        rel[k] = (float)(a / (1e-5 + fn));
    }
}

// ---------------- host ----------------
typedef CUresult (*PFN_tmEncode)(CUtensorMap*, CUtensorMapDataType, cuuint32_t, void*,
                                 const cuuint64_t*, const cuuint64_t*, const cuuint32_t*,
                                 const cuuint32_t*, CUtensorMapInterleave, CUtensorMapSwizzle,
                                 CUtensorMapL2promotion, CUtensorMapFloatOOBfill);

static void make_tm(PFN_tmEncode enc, CUtensorMap* tm, void* ptr, uint32_t box1) {
    cuuint64_t dims[2] = { (cuuint64_t)D, (cuuint64_t)D };
    cuuint64_t strides[1] = { (cuuint64_t)D * sizeof(__nv_bfloat16) };
    cuuint32_t box[2] = { TKt, box1 };
    cuuint32_t es[2] = { 1, 1 };
    enc(tm, CU_TENSOR_MAP_DATA_TYPE_BFLOAT16, 2, ptr, dims, strides, box, es,
        CU_TENSOR_MAP_INTERLEAVE_NONE, CU_TENSOR_MAP_SWIZZLE_128B,
        CU_TENSOR_MAP_L2_PROMOTION_L2_128B, CU_TENSOR_MAP_FLOAT_OOB_FILL_NONE);
}

extern "C" void kernel_launch(void* const* d_in, const int* in_sizes, int n_in,
                              void* d_out, int out_size)
{
    const float* x0   = (const float*)d_in[0];
    const float* W    = (const float*)d_in[1];
    const float* bias = (const float*)d_in[2];

    float* out = (float*)d_out;
    float* res  = out;
    float* X    = out + (size_t)BSZ * D;
    float* rel  = out + (size_t)BSZ * D + (size_t)BSZ * MM * D;
    float* absd = rel + NITER;

    float *Fp, *Gp; __nv_bfloat16 *Ahip, *Alop, *Whip, *Wlop;
    double* normsp; unsigned *barp, *progp;
    cudaGetSymbolAddress((void**)&Fp, g_F);
    cudaGetSymbolAddress((void**)&Gp, g_G);
    cudaGetSymbolAddress((void**)&Ahip, g_Ahi);
    cudaGetSymbolAddress((void**)&Alop, g_Alo);
    cudaGetSymbolAddress((void**)&Whip, g_Whi);
    cudaGetSymbolAddress((void**)&Wlop, g_Wlo);
    cudaGetSymbolAddress((void**)&normsp, g_norms);
    cudaGetSymbolAddress((void**)&barp, g_bar);
    cudaGetSymbolAddress((void**)&progp, g_prog);

    PFN_tmEncode enc = nullptr;
    {
        void* fp = nullptr;
        cudaDriverEntryPointQueryResult qr;
        cudaGetDriverEntryPoint("cuTensorMapEncodeTiled", &fp, cudaEnableDefault, &qr);
        enc = (PFN_tmEncode)fp;
    }
    CUtensorMap tmAhi, tmAlo, tmWhi, tmWlo;
    make_tm(enc, &tmAhi, Ahip, TMt);
    make_tm(enc, &tmAlo, Alop, TMt);
    make_tm(enc, &tmWhi, Whip, TNt);
    make_tm(enc, &tmWlo, Wlop, TNt);

    cudaFuncSetAttribute(aa_persistent_kernel, cudaFuncAttributeMaxDynamicSharedMemorySize, SMEM_TOTAL);

    zero_norms_kernel<<<1, 64>>>(normsp, barp, progp);

    {
        dim3 blk(32, 32), grd(D / 32, D / 32);
        wsplit_kernel<<<grd, blk>>>(W, Whip, Wlop);
    }

    scatter_x0_kernel<<<(BSZ * D + 255) / 256, 256>>>(x0, X, Ahip, Alop);

    {
        dim3 grid(D / TNt, BSZ / TMt);   // (8, 16) = 128 CTAs, all co-resident
        aa_persistent_kernel<<<grid, 512, SMEM_TOTAL>>>(tmAhi, tmAlo, tmWhi, tmWlo, bias,
                                                        Fp, Gp, X, Ahip, Alop, res,
                                                        normsp, barp, progp);
    }

    trace_kernel<<<1, 32>>>(normsp, rel, absd);
}